// round 2
// baseline (speedup 1.0000x reference)
#include <cuda_runtime.h>
#include <cstdint>
#include <cstddef>

#define T_    4
#define B_    8
#define TB    32
#define C_    256
#define NSP   3136
#define HEADS 8
#define DH    32

// o factor: (2 * 32^-0.5) / 8, folded power-of-2 scalings are rounding-exact
#define O_FACTOR 0.044194173824159216f

// ---- scratch (static device memory; no allocations in kernel_launch) ----
__device__ unsigned char g_q[(size_t)TB * C_ * NSP];
__device__ unsigned char g_k[(size_t)TB * C_ * NSP];
__device__ unsigned char g_v[(size_t)TB * C_ * NSP];
__device__ unsigned char g_o[(size_t)TB * C_ * NSP];
__device__ float g_wq[C_ * C_];
__device__ float g_wk[C_ * C_];
__device__ float g_wv[C_ * C_];
__device__ float g_wp[C_ * C_];
__device__ float g_kv[TB * HEADS * DH * DH];

// ---------------------------------------------------------------------------
// Kernel 0: transpose weights to [k][m] layout (coalesced SGEMM A-loads).
// pw additionally scaled by 1/8 (exact) so projection reads raw uint8 ints.
// ---------------------------------------------------------------------------
__global__ void prep_weights(const float* __restrict__ qw,
                             const float* __restrict__ kw,
                             const float* __restrict__ vw,
                             const float* __restrict__ pw) {
    int idx = blockIdx.x * 256 + threadIdx.x;  // 0..65535, [o][c] row-major
    int o = idx >> 8;
    int c = idx & 255;
    int tidx = c * 256 + o;                    // [c][o]
    g_wq[tidx] = qw[idx];
    g_wk[tidx] = kw[idx];
    g_wv[tidx] = vw[idx];
    g_wp[tidx] = pw[idx] * 0.125f;
}

__device__ __forceinline__ float quant8(float x) {
    return fminf(fmaxf(rintf(x), 0.0f), 8.0f);   // rintf = round-half-to-even (matches jnp.round)
}

// ---------------------------------------------------------------------------
// Kernel 1: fused  xs=quant(x)/8  ->  {q,k,v} = W @ xs  -> BN -> quant -> uint8
// One block computes a 128(out-ch) x 128(spatial) tile; blockIdx.y selects
// which of the 3 weight matrices and which 128-row half; blockIdx.z = (t,b).
// ---------------------------------------------------------------------------
__global__ void __launch_bounds__(256, 2)
qkv_gemm(const float* __restrict__ x,
         const float* __restrict__ qbn,
         const float* __restrict__ kbn,
         const float* __restrict__ vbn) {
    int tb  = blockIdx.z;
    int mat = blockIdx.y >> 1;
    int m0  = (blockIdx.y & 1) << 7;
    int n0  = blockIdx.x << 7;

    const float* wT = (mat == 0) ? g_wq : (mat == 1) ? g_wk : g_wv;
    const float* bn = (mat == 0) ? qbn  : (mat == 1) ? kbn  : vbn;
    unsigned char* out = (mat == 0) ? g_q : (mat == 1) ? g_k : g_v;
    const float* xb = x + (size_t)tb * C_ * NSP;

    __shared__ float As[16][128];
    __shared__ float Bs[16][128];

    int tid = threadIdx.x;          // 256 threads = 16x16
    int tr  = tid >> 4;             // 0..15  (m)
    int tc  = tid & 15;             // 0..15  (n)

    float acc[8][8];
#pragma unroll
    for (int i = 0; i < 8; i++)
#pragma unroll
        for (int j = 0; j < 8; j++) acc[i][j] = 0.0f;

    for (int k0 = 0; k0 < C_; k0 += 16) {
        // A tile: wT[(k0+k)*256 + m0+m]  (coalesced, conflict-free store)
#pragma unroll
        for (int i = 0; i < 8; i++) {
            int idx = tid + (i << 8);
            int k = idx >> 7, m = idx & 127;
            As[k][m] = wT[(k0 + k) * 256 + m0 + m];
        }
        // B tile: xs computed on the fly from x
#pragma unroll
        for (int i = 0; i < 8; i++) {
            int idx = tid + (i << 8);
            int k = idx >> 7, n = idx & 127;
            int gn = n0 + n;
            float v = 0.0f;
            if (gn < NSP) {
                float xv = xb[(size_t)(k0 + k) * NSP + gn];
                v = quant8(xv) * 0.125f;
            }
            Bs[k][n] = v;
        }
        __syncthreads();

#pragma unroll
        for (int k = 0; k < 16; k++) {
            float4 a0 = *reinterpret_cast<const float4*>(&As[k][tr << 3]);
            float4 a1 = *reinterpret_cast<const float4*>(&As[k][(tr << 3) + 4]);
            float4 b0 = *reinterpret_cast<const float4*>(&Bs[k][tc << 3]);
            float4 b1 = *reinterpret_cast<const float4*>(&Bs[k][(tc << 3) + 4]);
            float a[8] = {a0.x, a0.y, a0.z, a0.w, a1.x, a1.y, a1.z, a1.w};
            float b[8] = {b0.x, b0.y, b0.z, b0.w, b1.x, b1.y, b1.z, b1.w};
#pragma unroll
            for (int i = 0; i < 8; i++)
#pragma unroll
                for (int j = 0; j < 8; j++) acc[i][j] += a[i] * b[j];
        }
        __syncthreads();
    }

    // Epilogue: BN (separate mul+add, matching reference's non-fused rounding),
    // quant, store integer 0..8 as uint8.
#pragma unroll
    for (int i = 0; i < 8; i++) {
        int ch = m0 + (tr << 3) + i;
        float gamma = bn[ch], beta = bn[256 + ch], mean = bn[512 + ch], var = bn[768 + ch];
        float s = gamma / sqrtf(var + 1e-5f);
        float t = __fsub_rn(beta, __fmul_rn(mean, s));
        size_t base = ((size_t)tb * C_ + ch) * NSP;
#pragma unroll
        for (int j = 0; j < 8; j++) {
            int gn = n0 + (tc << 3) + j;
            if (gn < NSP) {
                float val = __fadd_rn(__fmul_rn(acc[i][j], s), t);
                out[base + gn] = (unsigned char)quant8(val);
            }
        }
    }
}

// ---------------------------------------------------------------------------
// Kernel 2: kv[d][e] = sum_n k_int[d][n] * v_int[e][n], stored as /64 (EXACT).
// One block per (t,b,head); 256 threads.
// ---------------------------------------------------------------------------
__global__ void __launch_bounds__(256)
kv_kernel() {
    int tbh = blockIdx.x;           // 0..255
    int tb = tbh >> 3, h = tbh & 7;
    const unsigned char* kp = g_k + ((size_t)tb * C_ + h * DH) * NSP;
    const unsigned char* vp = g_v + ((size_t)tb * C_ + h * DH) * NSP;

    __shared__ float ks[32][33];
    __shared__ float vs[32][33];

    int tid = threadIdx.x;
    int d  = tid & 31;
    int e0 = (tid >> 5) << 2;       // 8 groups of 4 e-columns
    float acc[4] = {0.f, 0.f, 0.f, 0.f};

    for (int nn0 = 0; nn0 < NSP; nn0 += 32) {
#pragma unroll
        for (int i = 0; i < 4; i++) {
            int idx = tid + (i << 8);
            int r = idx >> 5, c = idx & 31;
            ks[r][c] = (float)kp[(size_t)r * NSP + nn0 + c];
            vs[r][c] = (float)vp[(size_t)r * NSP + nn0 + c];
        }
        __syncthreads();
#pragma unroll
        for (int nn = 0; nn < 32; nn++) {
            float kd = ks[d][nn];
#pragma unroll
            for (int j = 0; j < 4; j++) acc[j] += kd * vs[e0 + j][nn];
        }
        __syncthreads();
    }
    float* kvout = g_kv + (size_t)tbh * (DH * DH);
#pragma unroll
    for (int j = 0; j < 4; j++) kvout[d * 32 + e0 + j] = acc[j] * (1.0f / 64.0f);
}

// ---------------------------------------------------------------------------
// Kernel 3: o[n][e] = (sum_d q_int[d][n] * kv[d][e]) * O_FACTOR -> quant -> uint8
// Thread = one spatial position; grid.y = (t,b,head).
// ---------------------------------------------------------------------------
__global__ void __launch_bounds__(256)
o_kernel() {
    int tbh = blockIdx.y;
    int tb = tbh >> 3, h = tbh & 7;
    __shared__ float kvs[DH * DH];
    for (int i = threadIdx.x; i < DH * DH; i += 256)
        kvs[i] = g_kv[(size_t)tbh * (DH * DH) + i];
    __syncthreads();

    int n = blockIdx.x * 256 + threadIdx.x;
    if (n >= NSP) return;

    const unsigned char* qp = g_q + ((size_t)tb * C_ + h * DH) * NSP + n;
    float o[DH];
#pragma unroll
    for (int e = 0; e < DH; e++) o[e] = 0.0f;
#pragma unroll
    for (int d = 0; d < DH; d++) {
        float qd = (float)qp[(size_t)d * NSP];
#pragma unroll
        for (int e = 0; e < DH; e++) o[e] += qd * kvs[d * 32 + e];
    }
    unsigned char* op = g_o + ((size_t)tb * C_ + h * DH) * NSP + n;
#pragma unroll
    for (int e = 0; e < DH; e++) {
        float val = o[e] * O_FACTOR;
        op[(size_t)e * NSP] = (unsigned char)quant8(val);
    }
}

// ---------------------------------------------------------------------------
// Kernel 4: out = BN(pw @ (o/8)); pw pre-scaled by 1/8, B tile = raw uint8.
// ---------------------------------------------------------------------------
__global__ void __launch_bounds__(256, 2)
proj_gemm(const float* __restrict__ pbn, float* __restrict__ out) {
    int tb = blockIdx.z;
    int m0 = blockIdx.y << 7;
    int n0 = blockIdx.x << 7;
    const unsigned char* ob = g_o + (size_t)tb * C_ * NSP;

    __shared__ float As[16][128];
    __shared__ float Bs[16][128];

    int tid = threadIdx.x;
    int tr  = tid >> 4;
    int tc  = tid & 15;

    float acc[8][8];
#pragma unroll
    for (int i = 0; i < 8; i++)
#pragma unroll
        for (int j = 0; j < 8; j++) acc[i][j] = 0.0f;

    for (int k0 = 0; k0 < C_; k0 += 16) {
#pragma unroll
        for (int i = 0; i < 8; i++) {
            int idx = tid + (i << 8);
            int k = idx >> 7, m = idx & 127;
            As[k][m] = g_wp[(k0 + k) * 256 + m0 + m];
        }
#pragma unroll
        for (int i = 0; i < 8; i++) {
            int idx = tid + (i << 8);
            int k = idx >> 7, n = idx & 127;
            int gn = n0 + n;
            Bs[k][n] = (gn < NSP) ? (float)ob[(size_t)(k0 + k) * NSP + gn] : 0.0f;
        }
        __syncthreads();

#pragma unroll
        for (int k = 0; k < 16; k++) {
            float4 a0 = *reinterpret_cast<const float4*>(&As[k][tr << 3]);
            float4 a1 = *reinterpret_cast<const float4*>(&As[k][(tr << 3) + 4]);
            float4 b0 = *reinterpret_cast<const float4*>(&Bs[k][tc << 3]);
            float4 b1 = *reinterpret_cast<const float4*>(&Bs[k][(tc << 3) + 4]);
            float a[8] = {a0.x, a0.y, a0.z, a0.w, a1.x, a1.y, a1.z, a1.w};
            float b[8] = {b0.x, b0.y, b0.z, b0.w, b1.x, b1.y, b1.z, b1.w};
#pragma unroll
            for (int i = 0; i < 8; i++)
#pragma unroll
                for (int j = 0; j < 8; j++) acc[i][j] += a[i] * b[j];
        }
        __syncthreads();
    }

#pragma unroll
    for (int i = 0; i < 8; i++) {
        int ch = m0 + (tr << 3) + i;
        float gamma = pbn[ch], beta = pbn[256 + ch], mean = pbn[512 + ch], var = pbn[768 + ch];
        float s = gamma / sqrtf(var + 1e-5f);
        float t = __fsub_rn(beta, __fmul_rn(mean, s));
        size_t base = ((size_t)tb * C_ + ch) * NSP;
#pragma unroll
        for (int j = 0; j < 8; j++) {
            int gn = n0 + (tc << 3) + j;
            if (gn < NSP) {
                out[base + gn] = __fadd_rn(__fmul_rn(acc[i][j], s), t);
            }
        }
    }
}

// ---------------------------------------------------------------------------
extern "C" void kernel_launch(void* const* d_in, const int* in_sizes, int n_in,
                              void* d_out, int out_size) {
    const float* x   = (const float*)d_in[0];
    const float* qw  = (const float*)d_in[1];
    const float* qbn = (const float*)d_in[2];
    const float* kw  = (const float*)d_in[3];
    const float* kbn = (const float*)d_in[4];
    const float* vw  = (const float*)d_in[5];
    const float* vbn = (const float*)d_in[6];
    const float* pw  = (const float*)d_in[7];
    const float* pbn = (const float*)d_in[8];
    float* out = (float*)d_out;

    prep_weights<<<256, 256>>>(qw, kw, vw, pw);
    qkv_gemm<<<dim3(25, 6, TB), 256>>>(x, qbn, kbn, vbn);
    kv_kernel<<<TB * HEADS, 256>>>();
    o_kernel<<<dim3(13, TB * HEADS), 256>>>();
    proj_gemm<<<dim3(25, 2, TB), 256>>>(pbn, out);
}

// round 4
// speedup vs baseline: 2.9295x; 2.9295x over previous
#include <cuda_runtime.h>
#include <cuda_fp16.h>
#include <cstdint>
#include <cstddef>

#define TB    32
#define C_    256
#define NSP   3136
#define HEADS 8
#define DH    32
#define O_FACTOR 0.044194173824159216f

// ---------------- static scratch ----------------
__device__ unsigned char g_q[(size_t)TB * C_ * NSP];
__device__ unsigned char g_k[(size_t)TB * C_ * NSP];
__device__ unsigned char g_v[(size_t)TB * C_ * NSP];
__device__ __half g_xs[(size_t)TB * NSP * C_];    // [tb][n][c] quant(x)/8, fp16-exact
__device__ __half g_obf[(size_t)TB * NSP * C_];   // [tb][n][c] o ints 0..8
__device__ __half g_wA[2 * 768 * 256];            // qkv weights, 2-way fp16 split, [s][row][k]
__device__ __half g_wP[2 * 256 * 256];            // proj weights (x1/8), 2-way fp16 split
__device__ float g_kv[TB * HEADS * DH * DH];

// ---------------- helpers ----------------
__device__ __forceinline__ float quant8(float x) {
    return fminf(fmaxf(rintf(x), 0.0f), 8.0f);   // round-half-even, matches jnp.round
}
__device__ __forceinline__ uint32_t smem_u32(const void* p) {
    uint32_t a;
    asm("{ .reg .u64 t; cvta.to.shared.u64 t, %1; cvt.u32.u64 %0, t; }" : "=r"(a) : "l"(p));
    return a;
}
#define SWZ(x) ((x) ^ (((x) >> 3) & 0x70))

__device__ __forceinline__ void cp16(uint32_t s, const void* g, uint32_t nbytes) {
    asm volatile("cp.async.cg.shared.global [%0], [%1], 16, %2;"
                 :: "r"(s), "l"(g), "r"(nbytes) : "memory");
}
#define CP_COMMIT() asm volatile("cp.async.commit_group;" ::: "memory")
#define CP_WAIT1()  asm volatile("cp.async.wait_group 1;" ::: "memory")
#define CP_WAIT0()  asm volatile("cp.async.wait_group 0;" ::: "memory")

#define LDSM_X4(r0, r1, r2, r3, addr) \
    asm volatile("ldmatrix.sync.aligned.m8n8.x4.shared.b16 {%0,%1,%2,%3}, [%4];" \
                 : "=r"(r0), "=r"(r1), "=r"(r2), "=r"(r3) : "r"(addr))

#define MMA16816(c, a, b) \
    asm volatile("mma.sync.aligned.m16n8k16.row.col.f32.f16.f16.f32 " \
                 "{%0,%1,%2,%3}, {%4,%5,%6,%7}, {%8,%9}, {%0,%1,%2,%3};" \
                 : "+f"((c)[0]), "+f"((c)[1]), "+f"((c)[2]), "+f"((c)[3]) \
                 : "r"((a)[0]), "r"((a)[1]), "r"((a)[2]), "r"((a)[3]), \
                   "r"((b)[0]), "r"((b)[1]))

// ---------------------------------------------------------------------------
// Kernel 0: exact 2-way fp16 split of weights. qkv stacked [768][256]; proj
// weights pre-scaled by 1/8 (power-of-2, exact).
// ---------------------------------------------------------------------------
__global__ void split_weights(const float* __restrict__ qw, const float* __restrict__ kw,
                              const float* __restrict__ vw, const float* __restrict__ pw) {
    int idx = blockIdx.x * 256 + threadIdx.x;  // 0..262143
    float w;
    __half* dst;
    int stride;
    if (idx < 196608) {
        int row = idx >> 8, col = idx & 255;
        w = (row < 256) ? qw[row * 256 + col]
          : (row < 512) ? kw[(row - 256) * 256 + col]
                        : vw[(row - 512) * 256 + col];
        dst = g_wA + idx; stride = 196608;
    } else {
        int i2 = idx - 196608;
        w = pw[i2] * 0.125f;
        dst = g_wP + i2; stride = 65536;
    }
    __half h1 = __float2half_rn(w);
    float f1 = __half2float(h1);
    __half h2 = __float2half_rn(w - f1);
    dst[0] = h1; dst[stride] = h2;
}

// ---------------------------------------------------------------------------
// Kernel 1: xs = quant(x)/8 -> fp16, transposed to [tb][n][c].
// ---------------------------------------------------------------------------
__global__ void __launch_bounds__(256)
transpose_x(const float* __restrict__ x) {
    __shared__ __half tile[32][34];
    int tb = blockIdx.z;
    int c0 = blockIdx.y << 5;
    int n0 = blockIdx.x << 5;
    int tid = threadIdx.x;
    int cc = tid >> 5, nn = tid & 31;
#pragma unroll
    for (int i = 0; i < 4; i++) {
        int c = c0 + cc + i * 8;
        float v = x[((size_t)(tb * C_) + c) * NSP + n0 + nn];
        tile[cc + i * 8][nn] = __float2half_rn(quant8(v) * 0.125f);
    }
    __syncthreads();
    int cl = tid & 31, r = tid >> 5;
#pragma unroll
    for (int i = 0; i < 4; i++) {
        int n = n0 + r + i * 8;
        g_xs[((size_t)tb * NSP + n) * C_ + c0 + cl] = tile[cl][r + i * 8];
    }
}

// ---------------------------------------------------------------------------
// Kernel 2: HMMA GEMM (mma.sync m16n8k16). D[128m][128n] over K=512
// (2 fp16 splits x 256). 8 warps, warp tile 32m x 64n, K-chunk 64,
// cp.async double buffering, SW128-swizzled SMEM, ldmatrix.x4 frags.
// mode 0: qkv -> BN+quant -> uint8 g_q/g_k/g_v. mode 1: proj -> BN -> fp32 out.
// ---------------------------------------------------------------------------
__global__ void __launch_bounds__(256, 2)
mma_gemm(int mode, const float* __restrict__ bnA, const float* __restrict__ bnB,
         const float* __restrict__ bnC, float* __restrict__ outf) {
    extern __shared__ char smraw[];
    const uint32_t sbase = (smem_u32(smraw) + 127u) & ~127u;
    const uint32_t A_OFF = 0, B_OFF = 32768;   // each: 2 bufs x 16KB

    const int tid = threadIdx.x;
    const int lane = tid & 31;
    const int wid = tid >> 5;
    const int wm = wid >> 1;        // 0..3 -> 32 m-rows each
    const int wn = wid & 1;         // 0..1 -> 64 n-cols each
    const int n0 = blockIdx.x << 7;
    const int m0 = blockIdx.y << 7;
    const int tb = blockIdx.z;

    const __half* wsplit = mode ? g_wP : g_wA;
    const int wrows = mode ? 256 : 768;
    const __half* bsrc = (mode ? g_obf : g_xs) + (size_t)tb * NSP * C_;

    float acc[2][8][4];
#pragma unroll
    for (int i = 0; i < 2; i++)
#pragma unroll
        for (int j = 0; j < 8; j++)
#pragma unroll
            for (int l = 0; l < 4; l++) acc[i][j][l] = 0.0f;

    const int ks8 = tid & 7;          // 16B segment within 128B row
    const int rbase = tid >> 3;       // 0..31

    // ---- chunk loader: chunk c -> buffer buf ----
    auto load_chunk = [&](int c, int buf) {
        int s = c >> 2, kc = c & 3;
        const __half* abase = wsplit + ((size_t)s * wrows + m0) * 256 + kc * 64;
#pragma unroll
        for (int it = 0; it < 4; it++) {
            int row = it * 32 + rbase;
            uint32_t sa = sbase + A_OFF + buf * 16384 + SWZ(row * 128 + ks8 * 16);
            cp16(sa, abase + (size_t)row * 256 + ks8 * 8, 16);
        }
        const __half* bbase = bsrc + kc * 64 + ks8 * 8;
#pragma unroll
        for (int it = 0; it < 4; it++) {
            int row = it * 32 + rbase;
            int gn = n0 + row;
            uint32_t ok = (gn < NSP) ? 16u : 0u;
            uint32_t sa = sbase + B_OFF + buf * 16384 + SWZ(row * 128 + ks8 * 16);
            cp16(sa, bbase + (size_t)(ok ? gn : 0) * 256, ok);
        }
        CP_COMMIT();
    };

    load_chunk(0, 0);
#pragma unroll 1
    for (int c = 0; c < 8; c++) {
        if (c < 7) { load_chunk(c + 1, (c + 1) & 1); CP_WAIT1(); }
        else       { CP_WAIT0(); }
        __syncthreads();

        uint32_t Ab = sbase + A_OFF + (c & 1) * 16384;
        uint32_t Bb = sbase + B_OFF + (c & 1) * 16384;
#pragma unroll
        for (int ks = 0; ks < 4; ks++) {
            uint32_t a[2][4], b[8][2];
#pragma unroll
            for (int tm = 0; tm < 2; tm++) {
                int row = wm * 32 + tm * 16 + (lane & 15);
                uint32_t ad = Ab + SWZ(row * 128 + ks * 32 + (lane >> 4) * 16);
                LDSM_X4(a[tm][0], a[tm][1], a[tm][2], a[tm][3], ad);
            }
#pragma unroll
            for (int tp = 0; tp < 4; tp++) {
                int row = wn * 64 + tp * 16 + (lane & 15);
                uint32_t bd = Bb + SWZ(row * 128 + ks * 32 + (lane >> 4) * 16);
                uint32_t r0, r1, r2, r3;
                LDSM_X4(r0, r1, r2, r3, bd);
                b[2 * tp][0] = r0; b[2 * tp][1] = r2;
                b[2 * tp + 1][0] = r1; b[2 * tp + 1][1] = r3;
            }
#pragma unroll
            for (int tm = 0; tm < 2; tm++)
#pragma unroll
                for (int tn = 0; tn < 8; tn++)
                    MMA16816(acc[tm][tn], a[tm], b[tn]);
        }
        __syncthreads();
    }

    // ---- epilogue ----
#pragma unroll
    for (int tm = 0; tm < 2; tm++) {
#pragma unroll
        for (int h = 0; h < 2; h++) {
            int gm = m0 + wm * 32 + tm * 16 + (lane >> 2) + h * 8;
            const float* bn;
            unsigned char* out8 = nullptr;
            int ch;
            if (mode == 0) {
                int mat = gm >> 8;
                bn = (mat == 0) ? bnA : (mat == 1) ? bnB : bnC;
                out8 = (mat == 0) ? g_q : (mat == 1) ? g_k : g_v;
                ch = gm & 255;
            } else {
                bn = bnA;
                ch = gm;
            }
            float s_ = bn[ch] / sqrtf(bn[768 + ch] + 1e-5f);
            float t_ = __fsub_rn(bn[256 + ch], __fmul_rn(bn[512 + ch], s_));
            size_t base = ((size_t)(tb * C_) + ch) * NSP;
#pragma unroll
            for (int tn = 0; tn < 8; tn++) {
                int n = n0 + wn * 64 + tn * 8 + (lane & 3) * 2;
                if (n < NSP) {
                    float v0 = __fadd_rn(__fmul_rn(acc[tm][tn][2 * h + 0], s_), t_);
                    float v1 = __fadd_rn(__fmul_rn(acc[tm][tn][2 * h + 1], s_), t_);
                    if (mode == 0) {
                        uchar2 u;
                        u.x = (unsigned char)quant8(v0);
                        u.y = (unsigned char)quant8(v1);
                        *reinterpret_cast<uchar2*>(out8 + base + n) = u;
                    } else {
                        *reinterpret_cast<float2*>(outf + base + n) = make_float2(v0, v1);
                    }
                }
            }
        }
    }
}

// ---------------------------------------------------------------------------
// Kernel 3: kv[d][e] = sum_n k_int*v_int via dp4a (exact int), /64 as float.
// ---------------------------------------------------------------------------
__global__ void __launch_bounds__(256)
kv_kernel() {
    int tbh = blockIdx.x;
    int tb = tbh >> 3, h = tbh & 7;
    const unsigned char* kp = g_k + ((size_t)(tb * C_) + h * DH) * NSP;
    const unsigned char* vp = g_v + ((size_t)(tb * C_) + h * DH) * NSP;

    __shared__ uint32_t ks[32][9];
    __shared__ uint32_t vs[32][9];

    int tid = threadIdx.x;
    int lr = tid >> 3, lw = tid & 7;
    int d0 = (tid >> 5) * 4, e = tid & 31;
    int acc0 = 0, acc1 = 0, acc2 = 0, acc3 = 0;

    const unsigned char* kaddr = kp + (size_t)lr * NSP + lw * 4;
    const unsigned char* vaddr = vp + (size_t)lr * NSP + lw * 4;
    uint32_t kreg = *(const uint32_t*)(kaddr);
    uint32_t vreg = *(const uint32_t*)(vaddr);

    for (int nn0 = 0; nn0 < NSP; nn0 += 32) {
        __syncthreads();
        ks[lr][lw] = kreg;
        vs[lr][lw] = vreg;
        __syncthreads();
        if (nn0 + 32 < NSP) {
            kreg = *(const uint32_t*)(kaddr + nn0 + 32);
            vreg = *(const uint32_t*)(vaddr + nn0 + 32);
        }
#pragma unroll
        for (int ww = 0; ww < 8; ww++) {
            int vv = (int)vs[e][ww];
            acc0 = __dp4a((int)ks[d0 + 0][ww], vv, acc0);
            acc1 = __dp4a((int)ks[d0 + 1][ww], vv, acc1);
            acc2 = __dp4a((int)ks[d0 + 2][ww], vv, acc2);
            acc3 = __dp4a((int)ks[d0 + 3][ww], vv, acc3);
        }
    }
    float* o = g_kv + (size_t)tbh * (DH * DH);
    o[(d0 + 0) * 32 + e] = (float)acc0 * (1.0f / 64.0f);
    o[(d0 + 1) * 32 + e] = (float)acc1 * (1.0f / 64.0f);
    o[(d0 + 2) * 32 + e] = (float)acc2 * (1.0f / 64.0f);
    o[(d0 + 3) * 32 + e] = (float)acc3 * (1.0f / 64.0f);
}

// ---------------------------------------------------------------------------
// Kernel 4: o[n][e] = quant((sum_d q_int[d][n]*kv[d][e]) * O_FACTOR) -> fp16
// stored [tb][n][c] for the proj GEMM.
// ---------------------------------------------------------------------------
__global__ void __launch_bounds__(256)
o_kernel() {
    int tbh = blockIdx.y;
    int tb = tbh >> 3, h = tbh & 7;
    __shared__ float kvs[DH * DH];
    for (int i = threadIdx.x; i < DH * DH; i += 256)
        kvs[i] = g_kv[(size_t)tbh * (DH * DH) + i];
    __syncthreads();

    int n = blockIdx.x * 256 + threadIdx.x;
    if (n >= NSP) return;

    const unsigned char* qp = g_q + ((size_t)(tb * C_) + h * DH) * NSP + n;
    float qv[32];
#pragma unroll
    for (int d = 0; d < 32; d++) qv[d] = (float)qp[(size_t)d * NSP];

    float acc[32];
#pragma unroll
    for (int e = 0; e < 32; e++) acc[e] = 0.0f;
#pragma unroll
    for (int d = 0; d < 32; d++) {
        float qd = qv[d];
        const float4* row = reinterpret_cast<const float4*>(&kvs[d * 32]);
#pragma unroll
        for (int e4 = 0; e4 < 8; e4++) {
            float4 kk = row[e4];
            acc[e4 * 4 + 0] += qd * kk.x;
            acc[e4 * 4 + 1] += qd * kk.y;
            acc[e4 * 4 + 2] += qd * kk.z;
            acc[e4 * 4 + 3] += qd * kk.w;
        }
    }

    uint32_t w[16];
#pragma unroll
    for (int e2 = 0; e2 < 16; e2++) {
        unsigned short lo = __half_as_ushort(__float2half_rn(quant8(acc[e2 * 2 + 0] * O_FACTOR)));
        unsigned short hi = __half_as_ushort(__float2half_rn(quant8(acc[e2 * 2 + 1] * O_FACTOR)));
        w[e2] = (uint32_t)lo | ((uint32_t)hi << 16);
    }
    __half* op = g_obf + ((size_t)tb * NSP + n) * C_ + h * DH;
#pragma unroll
    for (int g = 0; g < 4; g++)
        reinterpret_cast<uint4*>(op)[g] = make_uint4(w[g * 4], w[g * 4 + 1], w[g * 4 + 2], w[g * 4 + 3]);
}

// ---------------------------------------------------------------------------
extern "C" void kernel_launch(void* const* d_in, const int* in_sizes, int n_in,
                              void* d_out, int out_size) {
    const float* x   = (const float*)d_in[0];
    const float* qw  = (const float*)d_in[1];
    const float* qbn = (const float*)d_in[2];
    const float* kw  = (const float*)d_in[3];
    const float* kbn = (const float*)d_in[4];
    const float* vw  = (const float*)d_in[5];
    const float* vbn = (const float*)d_in[6];
    const float* pw  = (const float*)d_in[7];
    const float* pbn = (const float*)d_in[8];
    float* out = (float*)d_out;

    static int configured = 0;
    if (!configured) {
        cudaFuncSetAttribute(mma_gemm, cudaFuncAttributeMaxDynamicSharedMemorySize, 66048);
        configured = 1;
    }

    split_weights<<<1024, 256>>>(qw, kw, vw, pw);
    transpose_x<<<dim3(98, 8, TB), 256>>>(x);
    mma_gemm<<<dim3(25, 6, TB), 256, 66048>>>(0, qbn, kbn, vbn, nullptr);
    kv_kernel<<<TB * HEADS, 256>>>();
    o_kernel<<<dim3(13, TB * HEADS), 256>>>();
    mma_gemm<<<dim3(25, 2, TB), 256, 66048>>>(1, pbn, nullptr, nullptr, out);
}

// round 5
// speedup vs baseline: 3.0817x; 1.0520x over previous
#include <cuda_runtime.h>
#include <cuda_fp16.h>
#include <cstdint>
#include <cstddef>

#define TB    32
#define C_    256
#define NSP   3136
#define HEADS 8
#define DH    32
#define O_FACTOR 0.044194173824159216f

// ---------------- static scratch ----------------
__device__ unsigned char g_q[(size_t)TB * C_ * NSP];
__device__ unsigned char g_k[(size_t)TB * C_ * NSP];
__device__ unsigned char g_v[(size_t)TB * C_ * NSP];
__device__ __half g_xs[(size_t)TB * NSP * C_];    // [tb][n][c] quant(x)/8, fp16-exact
__device__ __half g_obf[(size_t)TB * NSP * C_];   // [tb][n][c] o ints 0..8
__device__ __half g_wA[2 * 768 * 256];            // qkv weights, 2-way fp16 split
__device__ __half g_wP[2 * 256 * 256];            // proj weights (x1/8), 2-way fp16 split
__device__ int g_kvi[TB * HEADS * DH * DH];       // exact integer kv accumulators

// ---------------- helpers ----------------
__device__ __forceinline__ float quant8(float x) {
    return fminf(fmaxf(rintf(x), 0.0f), 8.0f);
}
__device__ __forceinline__ uint32_t smem_u32(const void* p) {
    uint32_t a;
    asm("{ .reg .u64 t; cvta.to.shared.u64 t, %1; cvt.u32.u64 %0, t; }" : "=r"(a) : "l"(p));
    return a;
}
#define SWZ(x) ((x) ^ (((x) >> 3) & 0x70))

__device__ __forceinline__ void cp16(uint32_t s, const void* g, uint32_t nbytes) {
    asm volatile("cp.async.cg.shared.global [%0], [%1], 16, %2;"
                 :: "r"(s), "l"(g), "r"(nbytes) : "memory");
}
#define CP_COMMIT() asm volatile("cp.async.commit_group;" ::: "memory")
#define CP_WAIT1()  asm volatile("cp.async.wait_group 1;" ::: "memory")
#define CP_WAIT0()  asm volatile("cp.async.wait_group 0;" ::: "memory")

#define LDSM_X4(r0, r1, r2, r3, addr) \
    asm volatile("ldmatrix.sync.aligned.m8n8.x4.shared.b16 {%0,%1,%2,%3}, [%4];" \
                 : "=r"(r0), "=r"(r1), "=r"(r2), "=r"(r3) : "r"(addr))

#define MMA16816(c, a, b) \
    asm volatile("mma.sync.aligned.m16n8k16.row.col.f32.f16.f16.f32 " \
                 "{%0,%1,%2,%3}, {%4,%5,%6,%7}, {%8,%9}, {%0,%1,%2,%3};" \
                 : "+f"((c)[0]), "+f"((c)[1]), "+f"((c)[2]), "+f"((c)[3]) \
                 : "r"((a)[0]), "r"((a)[1]), "r"((a)[2]), "r"((a)[3]), \
                   "r"((b)[0]), "r"((b)[1]))

// ---------------------------------------------------------------------------
// Kernel 0: exact 2-way fp16 split of weights + zero the kv int accumulators.
// ---------------------------------------------------------------------------
__global__ void split_weights(const float* __restrict__ qw, const float* __restrict__ kw,
                              const float* __restrict__ vw, const float* __restrict__ pw) {
    int idx = blockIdx.x * 256 + threadIdx.x;  // 0..262143
    g_kvi[idx] = 0;                            // 262144 == TB*HEADS*DH*DH
    float w;
    __half* dst;
    int stride;
    if (idx < 196608) {
        int row = idx >> 8, col = idx & 255;
        w = (row < 256) ? qw[row * 256 + col]
          : (row < 512) ? kw[(row - 256) * 256 + col]
                        : vw[(row - 512) * 256 + col];
        dst = g_wA + idx; stride = 196608;
    } else {
        int i2 = idx - 196608;
        w = pw[i2] * 0.125f;
        dst = g_wP + i2; stride = 65536;
    }
    __half h1 = __float2half_rn(w);
    float f1 = __half2float(h1);
    __half h2 = __float2half_rn(w - f1);
    dst[0] = h1; dst[stride] = h2;
}

// ---------------------------------------------------------------------------
// Kernel 1: xs = quant(x)/8 -> fp16, transposed to [tb][n][c].
// ---------------------------------------------------------------------------
__global__ void __launch_bounds__(256)
transpose_x(const float* __restrict__ x) {
    __shared__ __half tile[32][34];
    int tb = blockIdx.z;
    int c0 = blockIdx.y << 5;
    int n0 = blockIdx.x << 5;
    int tid = threadIdx.x;
    int cc = tid >> 5, nn = tid & 31;
#pragma unroll
    for (int i = 0; i < 4; i++) {
        int c = c0 + cc + i * 8;
        float v = x[((size_t)(tb * C_) + c) * NSP + n0 + nn];
        tile[cc + i * 8][nn] = __float2half_rn(quant8(v) * 0.125f);
    }
    __syncthreads();
    int cl = tid & 31, r = tid >> 5;
#pragma unroll
    for (int i = 0; i < 4; i++) {
        int n = n0 + r + i * 8;
        g_xs[((size_t)tb * NSP + n) * C_ + c0 + cl] = tile[cl][r + i * 8];
    }
}

// ---------------------------------------------------------------------------
// Kernel 2: HMMA GEMM. B tile (128n x 256k, 64KB) loaded ONCE and kept
// resident; A streamed double-buffered over 8 chunks (2 fp16 splits x 4).
// mode 0: qkv -> BN+quant -> uint8. mode 1: proj -> BN -> fp32 out.
// ---------------------------------------------------------------------------
__global__ void __launch_bounds__(256, 2)
mma_gemm(int mode, const float* __restrict__ bnA, const float* __restrict__ bnB,
         const float* __restrict__ bnC, float* __restrict__ outf) {
    extern __shared__ char smraw[];
    const uint32_t sbase = (smem_u32(smraw) + 1023u) & ~1023u;
    const uint32_t B_OFF = 0, A_OFF = 65536;   // B: 4 blocks x 16KB; A: 2 bufs x 16KB

    const int tid = threadIdx.x;
    const int lane = tid & 31;
    const int wid = tid >> 5;
    const int wm = wid >> 1;
    const int wn = wid & 1;
    const int n0 = blockIdx.x << 7;
    const int m0 = blockIdx.y << 7;
    const int tb = blockIdx.z;

    const __half* wsplit = mode ? g_wP : g_wA;
    const int wrows = mode ? 256 : 768;
    const __half* bsrc = (mode ? g_obf : g_xs) + (size_t)tb * NSP * C_;

    float acc[2][8][4];
#pragma unroll
    for (int i = 0; i < 2; i++)
#pragma unroll
        for (int j = 0; j < 8; j++)
#pragma unroll
            for (int l = 0; l < 4; l++) acc[i][j][l] = 0.0f;

    const int ks8 = tid & 7;
    const int rbase = tid >> 3;

    auto load_chunkA = [&](int c, int buf) {
        int s = c >> 2, kc = c & 3;
        const __half* abase = wsplit + ((size_t)s * wrows + m0) * 256 + kc * 64;
#pragma unroll
        for (int it = 0; it < 4; it++) {
            int row = it * 32 + rbase;
            uint32_t sa = sbase + A_OFF + buf * 16384 + SWZ(row * 128 + ks8 * 16);
            cp16(sa, abase + (size_t)row * 256 + ks8 * 8, 16);
        }
    };

    // B tile: full K=256 for 128 n rows, 4 kc-blocks of 16KB (resident)
#pragma unroll
    for (int it = 0; it < 16; it++) {
        int seg = it * 256 + tid;          // 0..4095 16B segments
        int blk = seg >> 10;               // kc block
        int within = seg & 1023;
        int row = within >> 3;
        int k8 = within & 7;
        int gn = n0 + row;
        uint32_t ok = (gn < NSP) ? 16u : 0u;
        uint32_t sa = sbase + B_OFF + blk * 16384 + SWZ(row * 128 + k8 * 16);
        cp16(sa, bsrc + (size_t)gn * 256 + blk * 64 + k8 * 8, ok);
    }
    load_chunkA(0, 0);
    CP_COMMIT();               // group: B + A0
    load_chunkA(1, 1);
    CP_COMMIT();               // group: A1

#pragma unroll 1
    for (int c = 0; c < 8; c++) {
        if (c < 7) CP_WAIT1(); else CP_WAIT0();
        __syncthreads();

        uint32_t Ab = sbase + A_OFF + (c & 1) * 16384;
        uint32_t Bb = sbase + B_OFF + (c & 3) * 16384;
#pragma unroll
        for (int ks = 0; ks < 4; ks++) {
            uint32_t a[2][4], b[8][2];
#pragma unroll
            for (int tm = 0; tm < 2; tm++) {
                int row = wm * 32 + tm * 16 + (lane & 15);
                uint32_t ad = Ab + SWZ(row * 128 + ks * 32 + (lane >> 4) * 16);
                LDSM_X4(a[tm][0], a[tm][1], a[tm][2], a[tm][3], ad);
            }
#pragma unroll
            for (int tp = 0; tp < 4; tp++) {
                int row = wn * 64 + tp * 16 + (lane & 15);
                uint32_t bd = Bb + SWZ(row * 128 + ks * 32 + (lane >> 4) * 16);
                uint32_t r0, r1, r2, r3;
                LDSM_X4(r0, r1, r2, r3, bd);
                b[2 * tp][0] = r0; b[2 * tp][1] = r2;
                b[2 * tp + 1][0] = r1; b[2 * tp + 1][1] = r3;
            }
#pragma unroll
            for (int tm = 0; tm < 2; tm++)
#pragma unroll
                for (int tn = 0; tn < 8; tn++)
                    MMA16816(acc[tm][tn], a[tm], b[tn]);
        }
        __syncthreads();
        if (c + 2 <= 7) { load_chunkA(c + 2, (c + 2) & 1); CP_COMMIT(); }
    }

    // ---- epilogue ----
#pragma unroll
    for (int tm = 0; tm < 2; tm++) {
#pragma unroll
        for (int h = 0; h < 2; h++) {
            int gm = m0 + wm * 32 + tm * 16 + (lane >> 2) + h * 8;
            const float* bn;
            unsigned char* out8 = nullptr;
            int ch;
            if (mode == 0) {
                int mat = gm >> 8;
                bn = (mat == 0) ? bnA : (mat == 1) ? bnB : bnC;
                out8 = (mat == 0) ? g_q : (mat == 1) ? g_k : g_v;
                ch = gm & 255;
            } else {
                bn = bnA;
                ch = gm;
            }
            float s_ = bn[ch] / sqrtf(bn[768 + ch] + 1e-5f);
            float t_ = __fsub_rn(bn[256 + ch], __fmul_rn(bn[512 + ch], s_));
            size_t base = ((size_t)(tb * C_) + ch) * NSP;
#pragma unroll
            for (int tn = 0; tn < 8; tn++) {
                int n = n0 + wn * 64 + tn * 8 + (lane & 3) * 2;
                if (n < NSP) {
                    float v0 = __fadd_rn(__fmul_rn(acc[tm][tn][2 * h + 0], s_), t_);
                    float v1 = __fadd_rn(__fmul_rn(acc[tm][tn][2 * h + 1], s_), t_);
                    if (mode == 0) {
                        uchar2 u;
                        u.x = (unsigned char)quant8(v0);
                        u.y = (unsigned char)quant8(v1);
                        *reinterpret_cast<uchar2*>(out8 + base + n) = u;
                    } else {
                        *reinterpret_cast<float2*>(outf + base + n) = make_float2(v0, v1);
                    }
                }
            }
        }
    }
}

// ---------------------------------------------------------------------------
// Kernel 3: kv partial sums via dp4a (exact int), 7-way split over N,
// atomicAdd(int) into g_kvi (exact).
// ---------------------------------------------------------------------------
__global__ void __launch_bounds__(256)
kv_kernel() {
    int tbh = blockIdx.y;
    int tb = tbh >> 3, h = tbh & 7;
    int nstart = blockIdx.x * 448;               // 7 chunks x 448 = 3136
    const unsigned char* kp = g_k + ((size_t)(tb * C_) + h * DH) * NSP + nstart;
    const unsigned char* vp = g_v + ((size_t)(tb * C_) + h * DH) * NSP + nstart;

    __shared__ uint32_t ks[32][9];
    __shared__ uint32_t vs[32][9];

    int tid = threadIdx.x;
    int lr = tid >> 3, lw = tid & 7;
    int d0 = (tid >> 5) * 4, e = tid & 31;
    int acc0 = 0, acc1 = 0, acc2 = 0, acc3 = 0;

    const unsigned char* kaddr = kp + (size_t)lr * NSP + lw * 4;
    const unsigned char* vaddr = vp + (size_t)lr * NSP + lw * 4;
    uint32_t kreg = *(const uint32_t*)(kaddr);
    uint32_t vreg = *(const uint32_t*)(vaddr);

#pragma unroll 1
    for (int it = 0; it < 14; it++) {
        __syncthreads();
        ks[lr][lw] = kreg;
        vs[lr][lw] = vreg;
        __syncthreads();
        if (it < 13) {
            kreg = *(const uint32_t*)(kaddr + (it + 1) * 32);
            vreg = *(const uint32_t*)(vaddr + (it + 1) * 32);
        }
#pragma unroll
        for (int ww = 0; ww < 8; ww++) {
            int vv = (int)vs[e][ww];
            acc0 = __dp4a((int)ks[d0 + 0][ww], vv, acc0);
            acc1 = __dp4a((int)ks[d0 + 1][ww], vv, acc1);
            acc2 = __dp4a((int)ks[d0 + 2][ww], vv, acc2);
            acc3 = __dp4a((int)ks[d0 + 3][ww], vv, acc3);
        }
    }
    int* o = g_kvi + (size_t)tbh * (DH * DH);
    atomicAdd(&o[(d0 + 0) * 32 + e], acc0);
    atomicAdd(&o[(d0 + 1) * 32 + e], acc1);
    atomicAdd(&o[(d0 + 2) * 32 + e], acc2);
    atomicAdd(&o[(d0 + 3) * 32 + e], acc3);
}

// ---------------------------------------------------------------------------
// Kernel 4: o = quant((q_int . kv) * O_FACTOR) -> fp16 [tb][n][c].
// 2 spatial positions per thread (uchar2 q loads, shared kv row reuse).
// ---------------------------------------------------------------------------
__global__ void __launch_bounds__(256)
o_kernel() {
    int tbh = blockIdx.y;
    int tb = tbh >> 3, h = tbh & 7;
    __shared__ float kvs[DH * DH];
    for (int i = threadIdx.x; i < DH * DH; i += 256)
        kvs[i] = (float)g_kvi[(size_t)tbh * (DH * DH) + i] * (1.0f / 64.0f);
    __syncthreads();

    int n = (blockIdx.x * 256 + threadIdx.x) * 2;
    if (n >= NSP) return;

    const unsigned char* qp = g_q + ((size_t)(tb * C_) + h * DH) * NSP + n;
    float a0[32], a1[32];
#pragma unroll
    for (int e = 0; e < 32; e++) { a0[e] = 0.0f; a1[e] = 0.0f; }

#pragma unroll
    for (int d = 0; d < 32; d++) {
        uchar2 qd = *reinterpret_cast<const uchar2*>(qp + (size_t)d * NSP);
        float qx = (float)qd.x, qy = (float)qd.y;
        const float4* row = reinterpret_cast<const float4*>(&kvs[d * 32]);
#pragma unroll
        for (int e4 = 0; e4 < 8; e4++) {
            float4 kk = row[e4];
            a0[e4 * 4 + 0] += qx * kk.x;  a1[e4 * 4 + 0] += qy * kk.x;
            a0[e4 * 4 + 1] += qx * kk.y;  a1[e4 * 4 + 1] += qy * kk.y;
            a0[e4 * 4 + 2] += qx * kk.z;  a1[e4 * 4 + 2] += qy * kk.z;
            a0[e4 * 4 + 3] += qx * kk.w;  a1[e4 * 4 + 3] += qy * kk.w;
        }
    }

    __half* op0 = g_obf + ((size_t)tb * NSP + n) * C_ + h * DH;
#pragma unroll
    for (int half = 0; half < 2; half++) {
        float* a = half ? a1 : a0;
        uint32_t w[16];
#pragma unroll
        for (int e2 = 0; e2 < 16; e2++) {
            unsigned short lo = __half_as_ushort(__float2half_rn(quant8(a[e2 * 2 + 0] * O_FACTOR)));
            unsigned short hi = __half_as_ushort(__float2half_rn(quant8(a[e2 * 2 + 1] * O_FACTOR)));
            w[e2] = (uint32_t)lo | ((uint32_t)hi << 16);
        }
        __half* op = op0 + half * C_;
#pragma unroll
        for (int g = 0; g < 4; g++)
            reinterpret_cast<uint4*>(op)[g] = make_uint4(w[g * 4], w[g * 4 + 1], w[g * 4 + 2], w[g * 4 + 3]);
    }
}

// ---------------------------------------------------------------------------
extern "C" void kernel_launch(void* const* d_in, const int* in_sizes, int n_in,
                              void* d_out, int out_size) {
    const float* x   = (const float*)d_in[0];
    const float* qw  = (const float*)d_in[1];
    const float* qbn = (const float*)d_in[2];
    const float* kw  = (const float*)d_in[3];
    const float* kbn = (const float*)d_in[4];
    const float* vw  = (const float*)d_in[5];
    const float* vbn = (const float*)d_in[6];
    const float* pw  = (const float*)d_in[7];
    const float* pbn = (const float*)d_in[8];
    float* out = (float*)d_out;

    static int configured = 0;
    if (!configured) {
        cudaFuncSetAttribute(mma_gemm, cudaFuncAttributeMaxDynamicSharedMemorySize, 99328);
        configured = 1;
    }

    split_weights<<<1024, 256>>>(qw, kw, vw, pw);
    transpose_x<<<dim3(98, 8, TB), 256>>>(x);
    mma_gemm<<<dim3(25, 6, TB), 256, 99328>>>(0, qbn, kbn, vbn, nullptr);
    kv_kernel<<<dim3(7, TB * HEADS), 256>>>();
    o_kernel<<<dim3(7, TB * HEADS), 256>>>();
    mma_gemm<<<dim3(25, 2, TB), 256, 99328>>>(1, pbn, nullptr, nullptr, out);
}